// round 17
// baseline (speedup 1.0000x reference)
#include <cuda_runtime.h>
#include <math.h>
#include <stdint.h>

// Problem-fixed sizes
#define PN 200000
#define PE 800000
#define LN 100000
#define LE 400000
#define NB 512

// ---------------- scratch (static device globals; no allocation) ----------------
__device__ float g_pA[(size_t)PN * 256];
__device__ float g_pC[(size_t)PN * 256];
__device__ float g_lA[(size_t)LN * 256];
__device__ float g_lC[(size_t)LN * 256];
// p-branch CSR
__device__ float g_pdinv[PN];
__device__ int   g_pcnt[PN];
__device__ int   g_prp[PN];
__device__ int   g_pcursor[PN];
__device__ int   g_pesrc[PE];
__device__ int   g_ppart[1024];
// l-branch CSR
__device__ float g_ldinv[LN];
__device__ int   g_lcnt[LN];
__device__ int   g_lrp[LN];
__device__ int   g_lcursor[LN];
__device__ int   g_lesrc[LE];
__device__ int   g_lpart[1024];

__device__ float g_cat[NB * 512];
__device__ float g_fc1[NB * 1024];
__device__ float g_fc2[NB * 512];

// ---------------- CSR build ----------------
__global__ void zero_i(int* p, int n) {
    int i = blockIdx.x * blockDim.x + threadIdx.x;
    if (i < n) p[i] = 0;
}
__global__ void hist_k(int* cnt, const int* __restrict__ dst, int E) {
    int i = blockIdx.x * blockDim.x + threadIdx.x;
    if (i < E) atomicAdd(&cnt[dst[i]], 1);
}
__global__ __launch_bounds__(1024) void scan1(const int* __restrict__ in, int* __restrict__ out,
                                              int* __restrict__ part, int n) {
    __shared__ int s[1024];
    int i = blockIdx.x * 1024 + threadIdx.x;
    int v = (i < n) ? in[i] : 0;
    s[threadIdx.x] = v;
    __syncthreads();
    for (int off = 1; off < 1024; off <<= 1) {
        int t = (threadIdx.x >= off) ? s[threadIdx.x - off] : 0;
        __syncthreads();
        s[threadIdx.x] += t;
        __syncthreads();
    }
    if (i < n) out[i] = s[threadIdx.x] - v;
    if (threadIdx.x == 1023) part[blockIdx.x] = s[1023];
}
__global__ __launch_bounds__(256) void scan2(int* part, int nb) {
    __shared__ int s[256];
    int v = (threadIdx.x < nb) ? part[threadIdx.x] : 0;
    s[threadIdx.x] = v;
    __syncthreads();
    for (int off = 1; off < 256; off <<= 1) {
        int t = (threadIdx.x >= off) ? s[threadIdx.x - off] : 0;
        __syncthreads();
        s[threadIdx.x] += t;
        __syncthreads();
    }
    if (threadIdx.x < nb) part[threadIdx.x] = s[threadIdx.x] - v;
}
__global__ __launch_bounds__(1024) void scan3(int* __restrict__ out, const int* __restrict__ part,
                                              int* __restrict__ cursor, int n) {
    int i = blockIdx.x * 1024 + threadIdx.x;
    if (i < n) {
        int v = out[i] + part[blockIdx.x];
        out[i] = v;
        cursor[i] = v;
    }
}
__global__ void bucket_fill(const int* __restrict__ src, const int* __restrict__ dst,
                            int* __restrict__ cursor, int* __restrict__ esrc, int E) {
    int i = blockIdx.x * blockDim.x + threadIdx.x;
    if (i < E) {
        int pos = atomicAdd(&cursor[dst[i]], 1);
        esrc[pos] = src[i];
    }
}
__global__ void dinv_k(float* dinv, const int* __restrict__ cnt, int n) {
    int i = blockIdx.x * blockDim.x + threadIdx.x;
    if (i < n) dinv[i] = rsqrtf(1.0f + (float)cnt[i]);
}

// ---------------- tf32 helpers ----------------
__device__ __forceinline__ float to_tf32(float x) {
    float r;
    asm("cvt.rna.tf32.f32 %0, %1;" : "=f"(r) : "f"(x));
    return r;
}

// ---------------- tf32 tensor-core GEMM, BN=128 --------------------------------
__global__ __launch_bounds__(256) void sgemm_tf32(
    const float* __restrict__ A, const float* __restrict__ Bm,
    int M, int N, int K,
    float* __restrict__ C,
    const float* __restrict__ outscale,
    const float* __restrict__ bias, int do_relu)
{
    __shared__ float As[128][20];
    __shared__ float Bs[16][132];
    const int tid = threadIdx.x;
    const int lane = tid & 31;
    const int warp = tid >> 5;
    const int wm = warp & 1;
    const int wn = warp >> 1;
    const int row0 = blockIdx.y * 128;
    const int col0 = blockIdx.x * 128;

    float c[4][4][4];
    #pragma unroll
    for (int mt = 0; mt < 4; mt++)
        #pragma unroll
        for (int nt = 0; nt < 4; nt++)
            #pragma unroll
            for (int r = 0; r < 4; r++) c[mt][nt][r] = 0.f;

    const int qr = lane >> 2;
    const int qc = lane & 3;

    for (int kk = 0; kk < K; kk += 16) {
        #pragma unroll
        for (int f = tid; f < 512; f += 256) {
            int m = f >> 2;
            int kq = (f & 3) * 4;
            int gr = row0 + m;
            float4 v = make_float4(0.f, 0.f, 0.f, 0.f);
            if (gr < M)
                v = *reinterpret_cast<const float4*>(&A[(size_t)gr * K + kk + kq]);
            As[m][kq + 0] = to_tf32(v.x);
            As[m][kq + 1] = to_tf32(v.y);
            As[m][kq + 2] = to_tf32(v.z);
            As[m][kq + 3] = to_tf32(v.w);
        }
        #pragma unroll
        for (int f = tid; f < 512; f += 256) {
            int k = f >> 5;
            int nq = (f & 31) * 4;
            float4 v = *reinterpret_cast<const float4*>(&Bm[(size_t)(kk + k) * N + col0 + nq]);
            Bs[k][nq + 0] = to_tf32(v.x);
            Bs[k][nq + 1] = to_tf32(v.y);
            Bs[k][nq + 2] = to_tf32(v.z);
            Bs[k][nq + 3] = to_tf32(v.w);
        }
        __syncthreads();

        #pragma unroll
        for (int ks = 0; ks < 16; ks += 8) {
            uint32_t af[4][4];
            #pragma unroll
            for (int mt = 0; mt < 4; mt++) {
                int r = wm * 64 + mt * 16 + qr;
                af[mt][0] = __float_as_uint(As[r][ks + qc]);
                af[mt][1] = __float_as_uint(As[r + 8][ks + qc]);
                af[mt][2] = __float_as_uint(As[r][ks + qc + 4]);
                af[mt][3] = __float_as_uint(As[r + 8][ks + qc + 4]);
            }
            uint32_t bf[4][2];
            #pragma unroll
            for (int nt = 0; nt < 4; nt++) {
                int cb = wn * 32 + nt * 8 + qr;
                bf[nt][0] = __float_as_uint(Bs[ks + qc][cb]);
                bf[nt][1] = __float_as_uint(Bs[ks + 4 + qc][cb]);
            }
            #pragma unroll
            for (int mt = 0; mt < 4; mt++)
                #pragma unroll
                for (int nt = 0; nt < 4; nt++) {
                    asm volatile(
                        "mma.sync.aligned.m16n8k8.row.col.f32.tf32.tf32.f32 "
                        "{%0,%1,%2,%3}, {%4,%5,%6,%7}, {%8,%9}, {%0,%1,%2,%3};"
                        : "+f"(c[mt][nt][0]), "+f"(c[mt][nt][1]),
                          "+f"(c[mt][nt][2]), "+f"(c[mt][nt][3])
                        : "r"(af[mt][0]), "r"(af[mt][1]), "r"(af[mt][2]), "r"(af[mt][3]),
                          "r"(bf[nt][0]), "r"(bf[nt][1]));
                }
        }
        __syncthreads();
    }

    #pragma unroll
    for (int mt = 0; mt < 4; mt++) {
        #pragma unroll
        for (int nt = 0; nt < 4; nt++) {
            int r = row0 + wm * 64 + mt * 16 + qr;
            int cc = col0 + wn * 32 + nt * 8 + 2 * qc;
            if (r < M) {
                float os = outscale ? outscale[r] : 1.f;
                float v0 = c[mt][nt][0] + bias[cc];
                float v1 = c[mt][nt][1] + bias[cc + 1];
                if (do_relu) { v0 = fmaxf(v0, 0.f); v1 = fmaxf(v1, 0.f); }
                *reinterpret_cast<float2*>(&C[(size_t)r * N + cc]) = make_float2(v0 * os, v1 * os);
            }
            int r2 = r + 8;
            if (r2 < M) {
                float os = outscale ? outscale[r2] : 1.f;
                float v0 = c[mt][nt][2] + bias[cc];
                float v1 = c[mt][nt][3] + bias[cc + 1];
                if (do_relu) { v0 = fmaxf(v0, 0.f); v1 = fmaxf(v1, 0.f); }
                *reinterpret_cast<float2*>(&C[(size_t)r2 * N + cc]) = make_float2(v0 * os, v1 * os);
            }
        }
    }
}

// ---------------- tf32 GEMM, BN=64 (layer 1) -----------------------------------
template<int KP>
__global__ __launch_bounds__(256) void sgemm_tf32_n64(
    const float* __restrict__ A, const float* __restrict__ Bm,
    int M, int Kact,
    float* __restrict__ C,
    const float* __restrict__ outscale,
    const float* __restrict__ bias)
{
    constexpr int AS = KP + 4;
    __shared__ float As[128][AS];
    __shared__ float Bs[16][68];
    const int tid = threadIdx.x;
    const int lane = tid & 31;
    const int warp = tid >> 5;
    const int wm = warp & 1;
    const int wn = warp >> 1;
    const int row0 = blockIdx.y * 128;

    float c[4][2][4];
    #pragma unroll
    for (int mt = 0; mt < 4; mt++)
        #pragma unroll
        for (int nt = 0; nt < 2; nt++)
            #pragma unroll
            for (int r = 0; r < 4; r++) c[mt][nt][r] = 0.f;

    const int qr = lane >> 2;
    const int qc = lane & 3;

    #pragma unroll
    for (int f = tid; f < 128 * KP / 4; f += 256) {
        int m = f / (KP / 4);
        int kq = (f % (KP / 4)) * 4;
        int gr = row0 + m;
        float4 v = make_float4(0.f, 0.f, 0.f, 0.f);
        if (gr < M)
            v = *reinterpret_cast<const float4*>(&A[(size_t)gr * KP + kq]);
        As[m][kq + 0] = to_tf32(v.x);
        As[m][kq + 1] = to_tf32(v.y);
        As[m][kq + 2] = to_tf32(v.z);
        As[m][kq + 3] = to_tf32(v.w);
    }

    for (int kk = 0; kk < KP; kk += 16) {
        #pragma unroll
        for (int f = tid; f < 256; f += 256) {
            int k = f >> 4;
            int nq = (f & 15) * 4;
            int gk = kk + k;
            float4 v = make_float4(0.f, 0.f, 0.f, 0.f);
            if (gk < Kact)
                v = *reinterpret_cast<const float4*>(&Bm[(size_t)gk * 64 + nq]);
            Bs[k][nq + 0] = to_tf32(v.x);
            Bs[k][nq + 1] = to_tf32(v.y);
            Bs[k][nq + 2] = to_tf32(v.z);
            Bs[k][nq + 3] = to_tf32(v.w);
        }
        __syncthreads();

        #pragma unroll
        for (int ks = 0; ks < 16; ks += 8) {
            uint32_t af[4][4];
            #pragma unroll
            for (int mt = 0; mt < 4; mt++) {
                int r = wm * 64 + mt * 16 + qr;
                af[mt][0] = __float_as_uint(As[r][kk + ks + qc]);
                af[mt][1] = __float_as_uint(As[r + 8][kk + ks + qc]);
                af[mt][2] = __float_as_uint(As[r][kk + ks + qc + 4]);
                af[mt][3] = __float_as_uint(As[r + 8][kk + ks + qc + 4]);
            }
            uint32_t bf[2][2];
            #pragma unroll
            for (int nt = 0; nt < 2; nt++) {
                int cb = wn * 16 + nt * 8 + qr;
                bf[nt][0] = __float_as_uint(Bs[ks + qc][cb]);
                bf[nt][1] = __float_as_uint(Bs[ks + 4 + qc][cb]);
            }
            #pragma unroll
            for (int mt = 0; mt < 4; mt++)
                #pragma unroll
                for (int nt = 0; nt < 2; nt++) {
                    asm volatile(
                        "mma.sync.aligned.m16n8k8.row.col.f32.tf32.tf32.f32 "
                        "{%0,%1,%2,%3}, {%4,%5,%6,%7}, {%8,%9}, {%0,%1,%2,%3};"
                        : "+f"(c[mt][nt][0]), "+f"(c[mt][nt][1]),
                          "+f"(c[mt][nt][2]), "+f"(c[mt][nt][3])
                        : "r"(af[mt][0]), "r"(af[mt][1]), "r"(af[mt][2]), "r"(af[mt][3]),
                          "r"(bf[nt][0]), "r"(bf[nt][1]));
                }
        }
        __syncthreads();
    }

    #pragma unroll
    for (int mt = 0; mt < 4; mt++) {
        #pragma unroll
        for (int nt = 0; nt < 2; nt++) {
            int r = row0 + wm * 64 + mt * 16 + qr;
            int cc = wn * 16 + nt * 8 + 2 * qc;
            if (r < M) {
                float os = outscale[r];
                float v0 = fmaxf(c[mt][nt][0] + bias[cc], 0.f);
                float v1 = fmaxf(c[mt][nt][1] + bias[cc + 1], 0.f);
                *reinterpret_cast<float2*>(&C[(size_t)r * 64 + cc]) = make_float2(v0 * os, v1 * os);
            }
            int r2 = r + 8;
            if (r2 < M) {
                float os = outscale[r2];
                float v0 = fmaxf(c[mt][nt][2] + bias[cc], 0.f);
                float v1 = fmaxf(c[mt][nt][3] + bias[cc + 1], 0.f);
                *reinterpret_cast<float2*>(&C[(size_t)r2 * 64 + cc]) = make_float2(v0 * os, v1 * os);
            }
        }
    }
}

// ---------------- input gather (layer 1), 4-wide neighbor batching -------------
// out[d, 0:FIN] = dinv[d] * ( dinv[d]*x[d] + sum_e dinv[s_e]*x[s_e] ); tail zero
template <int FIN, int KP>
__global__ __launch_bounds__(256) void gather_in(
    const float* __restrict__ x, const int* __restrict__ rp, const int* __restrict__ cnt,
    const int* __restrict__ esrc, const float* __restrict__ dinv,
    float* __restrict__ out, int N)
{
    int node = (int)((blockIdx.x * blockDim.x + threadIdx.x) >> 5);
    if (node >= N) return;
    int lane = threadIdx.x & 31;
    constexpr int R = (KP + 31) / 32;
    float acc[R];
    float dn = dinv[node];

    #pragma unroll
    for (int j = 0; j < R; j++) {
        int cc = lane + 32 * j;
        acc[j] = (cc < FIN) ? dn * x[(size_t)node * FIN + cc] : 0.f;
    }

    int start = rp[node], len = cnt[node];
    for (int base = 0; base < len; base += 4) {
        int rem = len - base;
        // uniform scalar loads (warp-broadcast); masked via ds=0 for the tail
        int s0 = esrc[start + base];
        int s1 = (rem > 1) ? esrc[start + base + 1] : s0;
        int s2 = (rem > 2) ? esrc[start + base + 2] : s0;
        int s3 = (rem > 3) ? esrc[start + base + 3] : s0;
        float d0 = dinv[s0];
        float d1 = (rem > 1) ? dinv[s1] : 0.f;
        float d2 = (rem > 2) ? dinv[s2] : 0.f;
        float d3 = (rem > 3) ? dinv[s3] : 0.f;
        const float* p0 = x + (size_t)s0 * FIN;
        const float* p1 = x + (size_t)s1 * FIN;
        const float* p2 = x + (size_t)s2 * FIN;
        const float* p3 = x + (size_t)s3 * FIN;
        #pragma unroll
        for (int q = 0; q < R; q++) {
            int cc = lane + 32 * q;
            if (cc < FIN) {
                float v0 = p0[cc];
                float v1 = p1[cc];
                float v2 = p2[cc];
                float v3 = p3[cc];
                acc[q] = fmaf(d0, v0, acc[q]);
                acc[q] = fmaf(d1, v1, acc[q]);
                acc[q] = fmaf(d2, v2, acc[q]);
                acc[q] = fmaf(d3, v3, acc[q]);
            }
        }
    }

    #pragma unroll
    for (int j = 0; j < R; j++) {
        int cc = lane + 32 * j;
        if (cc < KP) out[(size_t)node * KP + cc] = acc[j] * dn;
    }
}

// ---------------- hidden gather (layers 2/3), 4-wide neighbor batching ---------
// out[d] = dinv[d] * ( y[d] + sum_e y[s_e] )
template <int F>
__global__ __launch_bounds__(256) void gather_mid(
    const float* __restrict__ h, const int* __restrict__ rp, const int* __restrict__ cnt,
    const int* __restrict__ esrc, const float* __restrict__ dinv,
    float* __restrict__ out, int N)
{
    int node = (int)((blockIdx.x * blockDim.x + threadIdx.x) >> 5);
    if (node >= N) return;
    int lane = threadIdx.x & 31;
    constexpr int R = F / 32;   // 2 or 4
    float acc[R];

    {
        const float* p = h + (size_t)node * F;
        if constexpr (F == 64) {
            float2 v = *reinterpret_cast<const float2*>(p + lane * 2);
            acc[0] = v.x; acc[1] = v.y;
        } else {
            float4 v = *reinterpret_cast<const float4*>(p + lane * 4);
            acc[0] = v.x; acc[1] = v.y; acc[2] = v.z; acc[3] = v.w;
        }
    }

    int start = rp[node], len = cnt[node];
    for (int base = 0; base < len; base += 4) {
        int rem = len - base;
        int s0 = esrc[start + base];
        int s1 = (rem > 1) ? esrc[start + base + 1] : s0;
        int s2 = (rem > 2) ? esrc[start + base + 2] : s0;
        int s3 = (rem > 3) ? esrc[start + base + 3] : s0;
        float m1 = (rem > 1) ? 1.f : 0.f;
        float m2 = (rem > 2) ? 1.f : 0.f;
        float m3 = (rem > 3) ? 1.f : 0.f;
        if constexpr (F == 64) {
            float2 v0 = *reinterpret_cast<const float2*>(h + (size_t)s0 * F + lane * 2);
            float2 v1 = *reinterpret_cast<const float2*>(h + (size_t)s1 * F + lane * 2);
            float2 v2 = *reinterpret_cast<const float2*>(h + (size_t)s2 * F + lane * 2);
            float2 v3 = *reinterpret_cast<const float2*>(h + (size_t)s3 * F + lane * 2);
            acc[0] += v0.x; acc[1] += v0.y;
            acc[0] = fmaf(m1, v1.x, acc[0]); acc[1] = fmaf(m1, v1.y, acc[1]);
            acc[0] = fmaf(m2, v2.x, acc[0]); acc[1] = fmaf(m2, v2.y, acc[1]);
            acc[0] = fmaf(m3, v3.x, acc[0]); acc[1] = fmaf(m3, v3.y, acc[1]);
        } else {
            float4 v0 = *reinterpret_cast<const float4*>(h + (size_t)s0 * F + lane * 4);
            float4 v1 = *reinterpret_cast<const float4*>(h + (size_t)s1 * F + lane * 4);
            float4 v2 = *reinterpret_cast<const float4*>(h + (size_t)s2 * F + lane * 4);
            float4 v3 = *reinterpret_cast<const float4*>(h + (size_t)s3 * F + lane * 4);
            acc[0] += v0.x; acc[1] += v0.y; acc[2] += v0.z; acc[3] += v0.w;
            acc[0] = fmaf(m1, v1.x, acc[0]); acc[1] = fmaf(m1, v1.y, acc[1]);
            acc[2] = fmaf(m1, v1.z, acc[2]); acc[3] = fmaf(m1, v1.w, acc[3]);
            acc[0] = fmaf(m2, v2.x, acc[0]); acc[1] = fmaf(m2, v2.y, acc[1]);
            acc[2] = fmaf(m2, v2.z, acc[2]); acc[3] = fmaf(m2, v2.w, acc[3]);
            acc[0] = fmaf(m3, v3.x, acc[0]); acc[1] = fmaf(m3, v3.y, acc[1]);
            acc[2] = fmaf(m3, v3.z, acc[2]); acc[3] = fmaf(m3, v3.w, acc[3]);
        }
    }

    float di = dinv[node];
    float* o = out + (size_t)node * F;
    if constexpr (F == 64) {
        *reinterpret_cast<float2*>(o + lane * 2) = make_float2(acc[0] * di, acc[1] * di);
    } else {
        *reinterpret_cast<float4*>(o + lane * 4) =
            make_float4(acc[0] * di, acc[1] * di, acc[2] * di, acc[3] * di);
    }
}

// ---------------- segmented mean-pool (batch is sorted) ------------------------
__global__ void pool_seg(const float* __restrict__ x, const int* __restrict__ batch,
                         int N, float* __restrict__ cat, int off)
{
    int b = blockIdx.x;
    int l = 0, r = N;
    while (l < r) { int m = (l + r) >> 1; if (batch[m] < b) l = m + 1; else r = m; }
    int start = l;
    r = N;
    while (l < r) { int m = (l + r) >> 1; if (batch[m] < b + 1) l = m + 1; else r = m; }
    int end = l;
    int c = threadIdx.x;
    float s = 0.f;
    for (int i = start; i < end; i++)
        s += x[(size_t)i * 256 + c];
    float cnt = (float)(end - start);
    cat[b * 512 + off + c] = s / fmaxf(cnt, 1.f);
}

// ---------------- final linear head ----------------
__global__ void out_kernel(const float* __restrict__ X, const float* __restrict__ W,
                           const float* __restrict__ bias, float* __restrict__ out)
{
    int b = blockIdx.x;
    __shared__ float red[256];
    float s = 0.f;
    for (int k = threadIdx.x; k < 512; k += 256)
        s += X[b * 512 + k] * W[k];
    red[threadIdx.x] = s;
    __syncthreads();
    for (int off = 128; off > 0; off >>= 1) {
        if (threadIdx.x < off) red[threadIdx.x] += red[threadIdx.x + off];
        __syncthreads();
    }
    if (threadIdx.x == 0) out[b] = red[0] + bias[0];
}

// ---------------- host side ----------------
static inline void gemm_tc(cudaStream_t st, const float* A, const float* B,
                           int M, int N, int K,
                           float* C0, const float* os, const float* bias, int relu)
{
    dim3 grid(N / 128, (M + 127) / 128);
    sgemm_tf32<<<grid, 256, 0, st>>>(A, B, M, N, K, C0, os, bias, relu);
}

template <int FIN, int KP>
static void run_branch(cudaStream_t st,
                       const float* x, int N, int E,
                       const int* src, const int* dst, const int* batch,
                       const float* W1, const float* b1,
                       const float* W2, const float* b2,
                       const float* W3, const float* b3,
                       float* A, float* C,
                       int* cnt, int* rp, int* cursor, int* esrc, int* part, float* dinv,
                       float* cat, int catoff)
{
    // CSR build (dst-keyed) + dinv
    zero_i<<<(N + 255) / 256, 256, 0, st>>>(cnt, N);
    hist_k<<<(E + 255) / 256, 256, 0, st>>>(cnt, dst, E);
    int nb = (N + 1023) / 1024;
    scan1<<<nb, 1024, 0, st>>>(cnt, rp, part, N);
    scan2<<<1, 256, 0, st>>>(part, nb);
    scan3<<<nb, 1024, 0, st>>>(rp, part, cursor, N);
    bucket_fill<<<(E + 255) / 256, 256, 0, st>>>(src, dst, cursor, esrc, E);
    dinv_k<<<(N + 255) / 256, 256, 0, st>>>(dinv, cnt, N);

    int gblocks = (N * 32 + 255) / 256;

    // layer 1: gather raw x into padded [N x KP], then tf32 GEMM KP->64
    gather_in<FIN, KP><<<gblocks, 256, 0, st>>>(x, rp, cnt, esrc, dinv, A, N);
    {
        dim3 grid(1, (N + 127) / 128);
        sgemm_tf32_n64<KP><<<grid, 256, 0, st>>>(A, W1, N, FIN, C, dinv, b1);
    }

    // layer 2: gather (64), tf32 GEMM 64->128
    gather_mid<64><<<gblocks, 256, 0, st>>>(C, rp, cnt, esrc, dinv, A, N);
    gemm_tc(st, A, W2, N, 128, 64, C, dinv, b2, 1);

    // layer 3: gather (128), tf32 GEMM 128->256, plain relu output
    gather_mid<128><<<gblocks, 256, 0, st>>>(C, rp, cnt, esrc, dinv, A, N);
    gemm_tc(st, A, W3, N, 256, 128, C, nullptr, b3, 1);

    // segmented mean pool -> cat[:, catoff:catoff+256]
    pool_seg<<<NB, 256, 0, st>>>(C, batch, N, cat, catoff);
}

extern "C" void kernel_launch(void* const* d_in, const int* in_sizes, int n_in,
                              void* d_out, int out_size)
{
    const float* p_x    = (const float*)d_in[0];
    const int*   p_ei   = (const int*)d_in[1];
    const int*   p_bat  = (const int*)d_in[2];
    const float* l_x    = (const float*)d_in[3];
    const int*   l_ei   = (const int*)d_in[4];
    const int*   l_bat  = (const int*)d_in[5];
    const float* p_W1 = (const float*)d_in[6],  *p_b1 = (const float*)d_in[7];
    const float* p_W2 = (const float*)d_in[8],  *p_b2 = (const float*)d_in[9];
    const float* p_W3 = (const float*)d_in[10], *p_b3 = (const float*)d_in[11];
    const float* l_W1 = (const float*)d_in[12], *l_b1 = (const float*)d_in[13];
    const float* l_W2 = (const float*)d_in[14], *l_b2 = (const float*)d_in[15];
    const float* l_W3 = (const float*)d_in[16], *l_b3 = (const float*)d_in[17];
    const float* fc1_W = (const float*)d_in[18], *fc1_b = (const float*)d_in[19];
    const float* fc2_W = (const float*)d_in[20], *fc2_b = (const float*)d_in[21];
    const float* out_W = (const float*)d_in[22], *out_b = (const float*)d_in[23];
    float* out = (float*)d_out;

    float *pA, *pC, *lA, *lC, *pdinv, *ldinv, *cat, *fc1, *fc2;
    int *pcnt, *prp, *pcursor, *pesrc, *ppart;
    int *lcnt, *lrp, *lcursor, *lesrc, *lpart;
    cudaGetSymbolAddress((void**)&pA, g_pA);
    cudaGetSymbolAddress((void**)&pC, g_pC);
    cudaGetSymbolAddress((void**)&lA, g_lA);
    cudaGetSymbolAddress((void**)&lC, g_lC);
    cudaGetSymbolAddress((void**)&pdinv, g_pdinv);
    cudaGetSymbolAddress((void**)&pcnt, g_pcnt);
    cudaGetSymbolAddress((void**)&prp, g_prp);
    cudaGetSymbolAddress((void**)&pcursor, g_pcursor);
    cudaGetSymbolAddress((void**)&pesrc, g_pesrc);
    cudaGetSymbolAddress((void**)&ppart, g_ppart);
    cudaGetSymbolAddress((void**)&ldinv, g_ldinv);
    cudaGetSymbolAddress((void**)&lcnt, g_lcnt);
    cudaGetSymbolAddress((void**)&lrp, g_lrp);
    cudaGetSymbolAddress((void**)&lcursor, g_lcursor);
    cudaGetSymbolAddress((void**)&lesrc, g_lesrc);
    cudaGetSymbolAddress((void**)&lpart, g_lpart);
    cudaGetSymbolAddress((void**)&cat, g_cat);
    cudaGetSymbolAddress((void**)&fc1, g_fc1);
    cudaGetSymbolAddress((void**)&fc2, g_fc2);

    // Fork a second stream for the l-branch (graph-capture fork-join).
    cudaStream_t s2;
    cudaStreamCreateWithFlags(&s2, cudaStreamNonBlocking);
    cudaEvent_t evFork, evJoin;
    cudaEventCreateWithFlags(&evFork, cudaEventDisableTiming);
    cudaEventCreateWithFlags(&evJoin, cudaEventDisableTiming);

    cudaEventRecord(evFork, 0);
    cudaStreamWaitEvent(s2, evFork, 0);

    // p branch on the origin stream
    run_branch<41, 48>((cudaStream_t)0, p_x, PN, PE, p_ei, p_ei + PE, p_bat,
                       p_W1, p_b1, p_W2, p_b2, p_W3, p_b3,
                       pA, pC, pcnt, prp, pcursor, pesrc, ppart, pdinv, cat, 0);

    // l branch concurrently on s2
    run_branch<78, 80>(s2, l_x, LN, LE, l_ei, l_ei + LE, l_bat,
                       l_W1, l_b1, l_W2, l_b2, l_W3, l_b3,
                       lA, lC, lcnt, lrp, lcursor, lesrc, lpart, ldinv, cat, 256);

    cudaEventRecord(evJoin, s2);
    cudaStreamWaitEvent(0, evJoin, 0);

    // MLP head (tf32) on the origin stream
    gemm_tc((cudaStream_t)0, cat, fc1_W, NB, 1024, 512, fc1, nullptr, fc1_b, 1);
    gemm_tc((cudaStream_t)0, fc1, fc2_W, NB, 512, 1024, fc2, nullptr, fc2_b, 1);
    out_kernel<<<NB, 256, 0, 0>>>(fc2, out_W, out_b, out);
}